// round 7
// baseline (speedup 1.0000x reference)
#include <cuda_runtime.h>
#include <cstdint>

#define IMG_N  2048
#define OW     2044
#define OH     2044
#define TW     128         // output cols per CTA
#define TH     12          // output rows per CTA
#define IR     16          // TH + 4 input rows
#define IC     132         // TW + 4 input cols
#define ICP    136         // padded col stride (bf16 elements)
#define NTH    192         // 16 col-groups x 12 rows

#define PLANES_U16 (IR * 16 * ICP)           // 34816 bf16
#define WOFF       (PLANES_U16 * 2)          // 69632 bytes
#define SMEM_BYTES (WOFF + 15 * 8 * 8)       // + padded weight pairs

typedef unsigned long long ull;
typedef unsigned int u32;

__device__ __forceinline__ void fma2(ull& acc, ull a, ull b) {
    asm("fma.rn.f32x2 %0, %1, %2, %0;" : "+l"(acc) : "l"(a), "l"(b));
}
__device__ __forceinline__ ull pack2(u32 lo, u32 hi) {
    ull r; asm("mov.b64 %0, {%1, %2};" : "=l"(r) : "r"(lo), "r"(hi)); return r;
}
__device__ __forceinline__ ull mkpair_lohi(u32 u) {
    ull r;
    asm("{.reg .b32 a, b;\n\t"
        "shl.b32 a, %1, 16;\n\t"
        "and.b32 b, %1, 0xFFFF0000;\n\t"
        "mov.b64 %0, {a, b};}" : "=l"(r) : "r"(u));
    return r;
}
__device__ __forceinline__ ull mkpair_cross(u32 u, u32 v) {
    ull r;
    asm("{.reg .b32 a, b;\n\t"
        "and.b32 a, %1, 0xFFFF0000;\n\t"
        "shl.b32 b, %2, 16;\n\t"
        "mov.b64 %0, {a, b};}" : "=l"(r) : "r"(u), "r"(v));
    return r;
}

// One z-pass: NZ outputs z in [z0, z0+NZ), planes k in [z0, z0+NZ+2), 8 cols/thread.
template<int NZ>
__device__ __forceinline__ void run_pass(const uint16_t* __restrict__ sp,
                                         const ull* __restrict__ wps,
                                         int r, int col0, int z0,
                                         ull acc[][4])
{
    #pragma unroll
    for (int z = 0; z < NZ; z++)
        #pragma unroll
        for (int p = 0; p < 4; p++) acc[z][p] = 0ull;

    #pragma unroll 1
    for (int i = 0; i < 5; i++) {
        // hoist all 15 weight pairs for this i (broadcast LDS)
        ull wv[15];
        #pragma unroll
        for (int d = 0; d < 3; d++) {
            const ull* wd = wps + (d * 5 + i) * 8;
            ulonglong2 w01 = *reinterpret_cast<const ulonglong2*>(wd);
            ulonglong2 w23 = *reinterpret_cast<const ulonglong2*>(wd + 2);
            wv[d*5+0] = w01.x; wv[d*5+1] = w01.y;
            wv[d*5+2] = w23.x; wv[d*5+3] = w23.y;
            wv[d*5+4] = wd[4];
        }

        const uint16_t* rowi = sp + ((r + i) * 16 + z0) * ICP + col0;

        #pragma unroll
        for (int kk = 0; kk < NZ + 2; kk++) {
            const u32* rk = reinterpret_cast<const u32*>(rowi + kk * ICP);
            uint2 ma = *reinterpret_cast<const uint2*>(rk);       // bf16 cols 0..3
            uint2 mb = *reinterpret_cast<const uint2*>(rk + 2);   // cols 4..7
            uint2 mc = *reinterpret_cast<const uint2*>(rk + 4);   // cols 8..11
            u32 wd0 = ma.x, wd1 = ma.y, wd2 = mb.x, wd3 = mb.y, wd4 = mc.x, wd5 = mc.y;

            ull S[11];
            S[0]  = mkpair_lohi (wd0);
            S[2]  = mkpair_lohi (wd1);
            S[4]  = mkpair_lohi (wd2);
            S[6]  = mkpair_lohi (wd3);
            S[8]  = mkpair_lohi (wd4);
            S[10] = mkpair_lohi (wd5);
            S[1]  = mkpair_cross(wd0, wd1);
            S[3]  = mkpair_cross(wd1, wd2);
            S[5]  = mkpair_cross(wd2, wd3);
            S[7]  = mkpair_cross(wd3, wd4);
            S[9]  = mkpair_cross(wd4, wd5);

            #pragma unroll
            for (int d = 0; d < 3; d++) {
                const int zz = kk - d;               // compile-time
                if (zz >= 0 && zz < NZ) {
                    #pragma unroll
                    for (int j = 0; j < 5; j++) {
                        const ull w = wv[d * 5 + j];
                        fma2(acc[zz][0], w, S[j + 0]);
                        fma2(acc[zz][1], w, S[j + 2]);
                        fma2(acc[zz][2], w, S[j + 4]);
                        fma2(acc[zz][3], w, S[j + 6]);
                    }
                }
            }
        }
    }
}

template<int NZ>
__device__ __forceinline__ void store_pass(float* __restrict__ out, int h, int w,
                                           int z0, float bv, ull acc[][4])
{
    if (h >= OH || w >= OW) return;
    #pragma unroll
    for (int zz = 0; zz < NZ; zz++) {
        size_t off = ((size_t)(z0 + zz) * OH + h) * OW + w;
        float2 a0 = *reinterpret_cast<const float2*>(&acc[zz][0]);
        float2 a1 = *reinterpret_cast<const float2*>(&acc[zz][1]);
        float2 a2 = *reinterpret_cast<const float2*>(&acc[zz][2]);
        float2 a3 = *reinterpret_cast<const float2*>(&acc[zz][3]);
        if (w + 8 <= OW) {
            *reinterpret_cast<float4*>(out + off)     = make_float4(a0.x+bv, a0.y+bv, a1.x+bv, a1.y+bv);
            *reinterpret_cast<float4*>(out + off + 4) = make_float4(a2.x+bv, a2.y+bv, a3.x+bv, a3.y+bv);
        } else {
            float vals[8] = { a0.x+bv, a0.y+bv, a1.x+bv, a1.y+bv,
                              a2.x+bv, a2.y+bv, a3.x+bv, a3.y+bv };
            #pragma unroll
            for (int c = 0; c < 8; c++)
                if (w + c < OW) out[off + c] = vals[c];
        }
    }
}

__global__ void __launch_bounds__(NTH, 3)
conv2dto3d_kernel(const int* __restrict__ x,
                  const float* __restrict__ weight,
                  const float* __restrict__ bias,
                  float* __restrict__ out)
{
    extern __shared__ unsigned char smem[];
    uint16_t* sp  = reinterpret_cast<uint16_t*>(smem);
    ull*      wps = reinterpret_cast<ull*>(smem + WOFF);

    const int tid   = threadIdx.x;
    const int wbase = blockIdx.x * TW;
    const int hbase = blockIdx.y * TH;

    if (tid < 75) {
        int d = tid / 25, rem = tid - d * 25;
        int i = rem / 5,  j = rem - i * 5;
        u32 wb = __float_as_uint(weight[tid]);
        wps[(d * 5 + i) * 8 + j] = pack2(wb, wb);
    }

    // ---- expand tile to bf16 bit planes (exact): sp[rr][k][cc] ----
    for (int pp = tid; pp < IR * (IC / 2); pp += NTH) {
        int rr = pp / (IC / 2);
        int c2 = (pp - rr * (IC / 2)) * 2;
        int ri = hbase + rr;     if (ri > IMG_N - 1) ri = IMG_N - 1;
        int c0 = wbase + c2;     if (c0 > IMG_N - 1) c0 = IMG_N - 1;
        int c1 = wbase + c2 + 1; if (c1 > IMG_N - 1) c1 = IMG_N - 1;
        u32 a0 = (u32)x[ri * IMG_N + c0];
        u32 a1 = (u32)x[ri * IMG_N + c1];
        #pragma unroll
        for (int k = 0; k < 16; k++) {
            u32 val = ((a0 >> k) & 1u) * 0x3F80u
                    | ((a1 >> k) & 1u) * 0x3F800000u;
            *reinterpret_cast<u32*>(sp + (rr * 16 + k) * ICP + c2) = val;
        }
    }
    __syncthreads();

    const int g = tid & 15;          // 16 column groups of 8
    const int r = tid >> 4;          // local row 0..11
    const int col0 = g * 8;
    const int h = hbase + r;
    const int w = wbase + col0;
    const float bv = bias[0];

    {
        ull acc[4][4];
        run_pass<4>(sp, wps, r, col0, 0, acc);
        store_pass<4>(out, h, w, 0, bv, acc);
        run_pass<4>(sp, wps, r, col0, 4, acc);
        store_pass<4>(out, h, w, 4, bv, acc);
        run_pass<4>(sp, wps, r, col0, 8, acc);
        store_pass<4>(out, h, w, 8, bv, acc);
    }
    {
        ull acc[2][4];
        run_pass<2>(sp, wps, r, col0, 12, acc);
        store_pass<2>(out, h, w, 12, bv, acc);
    }
}

extern "C" void kernel_launch(void* const* d_in, const int* in_sizes, int n_in,
                              void* d_out, int out_size)
{
    const int*   x      = (const int*)d_in[0];
    const float* weight = (const float*)d_in[1];
    const float* bias   = (const float*)d_in[2];
    float*       out    = (float*)d_out;

    cudaFuncSetAttribute(conv2dto3d_kernel,
                         cudaFuncAttributeMaxDynamicSharedMemorySize, SMEM_BYTES);

    dim3 grid((OW + TW - 1) / TW, (OH + TH - 1) / TH);   // 16 x 171
    conv2dto3d_kernel<<<grid, NTH, SMEM_BYTES>>>(x, weight, bias, out);
}